// round 11
// baseline (speedup 1.0000x reference)
#include <cuda_runtime.h>
#include <cuda_fp16.h>
#include <cstdint>

// y[m,n] = mask[m] ? x[m,:]·W_v[n,:] : x[m,:]·W_t[n,:]
// Mask-partitioned single GEMM, fp16 m16n8k16 mma.sync, fp32 accumulate.
// Operands pre-packed in MMA fragment order. This round: CTA tile 128x256
// (8 warps @ 64x64), halving smem traffic per MAC vs 128x128. 4-stage
// cp.async pipeline, 96KB smem, 1 CTA/SM.

#define M_TOTAL 32768
#define K_DIM   1024
#define N_DIM   1024
#define BM 128
#define BN 256
#define BK 32
#define NK (K_DIM / BK)              // 32 k-panels
#define THREADS 256
#define M_PAD 32896                  // 257 tiles * 128
#define NMT (M_PAD / BM)             // 257

#define PANEL_H  4096                // halves per 8KB panel (128 x 32k)
#define APANEL_B 8192
#define BPANEL_B 8192
#define STAGE_B  (APANEL_B + 2 * BPANEL_B)   // 24576
#define BSTAGES  4
#define DYN_SMEM (BSTAGES * STAGE_B)         // 98304

// ------------------------------------------------------------- device state
__device__ __half g_x[(size_t)M_PAD * K_DIM];    // [mtile][kpanel][frag order]
__device__ __half g_wv[(size_t)N_DIM * K_DIM];   // [ntile128][kpanel][frag order]
__device__ __half g_wt[(size_t)N_DIM * K_DIM];
__device__ int   g_perm[M_PAD];                  // slot -> source row (live only)
__device__ int   g_cv, g_ct;
__device__ int   g_mask_is_u8;

// Slot map: visual -> [0, nv) ascending; dead gap [nv, nv+128);
// text -> [nv+128, M_PAD) descending. Tile t uses W_v iff 128*t < nv.

// ------------------------------------------------------------- helpers
__device__ __forceinline__ bool mask_at(const unsigned char* m, int i) {
    return g_mask_is_u8 ? (m[i] != 0) : (((const int*)m)[i] != 0);
}

__device__ __forceinline__ uint32_t smem_u32(const void* p) {
    uint32_t a;
    asm("{ .reg .u64 t; cvta.to.shared.u64 t, %1; cvt.u32.u64 %0, t; }"
        : "=r"(a) : "l"(p));
    return a;
}

__device__ __forceinline__ void cp16(uint32_t saddr, const void* g) {
    asm volatile("cp.async.cg.shared.global [%0], [%1], 16;"
                 :: "r"(saddr), "l"(g) : "memory");
}

__device__ __forceinline__ void mma_f16(float* d, const uint32_t* a, const uint32_t* b) {
    asm volatile(
        "mma.sync.aligned.m16n8k16.row.col.f32.f16.f16.f32 "
        "{%0,%1,%2,%3}, {%4,%5,%6,%7}, {%8,%9}, {%0,%1,%2,%3};"
        : "+f"(d[0]), "+f"(d[1]), "+f"(d[2]), "+f"(d[3])
        : "r"(a[0]), "r"(a[1]), "r"(a[2]), "r"(a[3]), "r"(b[0]), "r"(b[1]));
}

// ------------------------------------------------------------- prep kernels
__global__ void k0_init(const unsigned char* __restrict__ m) {
    __shared__ int found;
    int tid = threadIdx.x;
    if (tid == 0) { found = 0; g_cv = 0; g_ct = 0; }
    __syncthreads();
    int local = 0;
    for (int i = tid; i < 8192; i += 1024)
        if (m[4 * i + 1] | m[4 * i + 2] | m[4 * i + 3]) local = 1;
    if (local) atomicOr(&found, 1);
    __syncthreads();
    if (tid == 0) g_mask_is_u8 = found;
}

// K12: one-pass slot assignment.
__global__ void k12_assign(const unsigned char* __restrict__ m) {
    int tid = threadIdx.x;
    int row = blockIdx.x * 256 + tid;
    int lane = tid & 31;
    bool mv = mask_at(m, row);
    unsigned bal = __ballot_sync(0xffffffffu, mv);
    int cv = __popc(bal);
    int lpv = __popc(bal & ((1u << lane) - 1));
    int lpt = lane - lpv;
    int baseV = 0, baseT = 0;
    if (lane == 0) {
        baseV = atomicAdd(&g_cv, cv);
        baseT = atomicAdd(&g_ct, 32 - cv);
    }
    baseV = __shfl_sync(0xffffffffu, baseV, 0);
    baseT = __shfl_sync(0xffffffffu, baseT, 0);
    int slot = mv ? (baseV + lpv) : (M_PAD - 1 - (baseT + lpt));
    g_perm[slot] = row;
}

// K3: x gather + fp16 convert -> A panels (smem-staged 16B reads).
__global__ void k3_xconv(const float* __restrict__ x) {
    __shared__ float sx[BM * BK];
    __shared__ int sperm[BM];
    const int mt = blockIdx.x, kp = blockIdx.y;
    const int tid = threadIdx.x;
    const int kbase = kp * BK;
    const int nv = g_cv;
    if (tid < BM) {
        int slot = mt * BM + tid;
        bool live = (slot < nv) || (slot >= nv + BM);
        sperm[tid] = live ? g_perm[slot] : -1;
    }
    __syncthreads();

    #pragma unroll
    for (int i = 0; i < 4; i++) {
        int idx = i * 256 + tid;          // 0..1023
        int row = idx >> 3, q = idx & 7;
        int src = sperm[row];
        float4 v = (src >= 0)
            ? *(const float4*)(x + (size_t)src * K_DIM + kbase + q * 4)
            : make_float4(0.f, 0.f, 0.f, 0.f);
        *(float4*)(sx + row * BK + q * 4) = v;
    }
    __syncthreads();

    __half* dst = g_x + ((size_t)mt * NK + kp) * PANEL_H;
    #pragma unroll
    for (int i = 0; i < 2; i++) {
        int h0 = (i * 256 + tid) * 8;
        int b = h0 >> 8;
        int rb = b >> 1, ks = b & 1;
        int lane = (h0 >> 3) & 31;
        int grp = lane >> 2, qid = lane & 3;
        __half vals[8];
        #pragma unroll
        for (int reg = 0; reg < 4; reg++) {
            int row = rb * 16 + grp + 8 * (reg & 1);
            int k   = ks * 16 + 2 * qid + 8 * (reg >> 1);
            vals[reg * 2 + 0] = __float2half_rn(sx[row * BK + k]);
            vals[reg * 2 + 1] = __float2half_rn(sx[row * BK + k + 1]);
        }
        *(uint4*)(dst + h0) = *(const uint4*)vals;
    }
}

// K4: weights -> fp16 B panels in fragment order (z selects matrix).
__global__ void k4_wconv(const float* __restrict__ Wv, const float* __restrict__ Wt) {
    const int nt = blockIdx.x, kp = blockIdx.y;
    const float* W = blockIdx.z ? Wt : Wv;
    __half* dst = (blockIdx.z ? g_wt : g_wv) + ((size_t)nt * NK + kp) * PANEL_H;
    const int tid = threadIdx.x;
    const int kbase = kp * BK;
    #pragma unroll
    for (int q = 0; q < 2; q++) {
        int h0 = tid * 8 + q * 2048;
        __half vals[8];
        #pragma unroll
        for (int j = 0; j < 8; j++) {
            int h = h0 + j;
            int blk = h >> 7;
            int nb = blk >> 1, ks = blk & 1;
            int lane = (h >> 2) & 31;
            int v = h & 3;
            int grp = lane >> 2, qid = lane & 3;
            int n = nt * 128 + nb * 8 + grp;
            int k = kbase + ks * 16 + 2 * qid + 8 * (v >> 1) + (v & 1);
            vals[j] = __float2half_rn(W[(size_t)n * K_DIM + k]);
        }
        *(uint4*)(dst + h0) = *(const uint4*)vals;
    }
}

// ------------------------------------------------------------- GEMM
extern __shared__ __align__(128) char dsmem[];

__global__ __launch_bounds__(THREADS, 1)
void gemm_kernel(float* __restrict__ out)
{
    const int tid  = threadIdx.x;
    const int warp = tid >> 5;
    const int lane = tid & 31;
    const int grp  = lane >> 2;
    const int qid  = lane & 3;
    const int wm   = warp >> 2;              // 0..1 (64 rows each)
    const int wn   = warp & 3;               // 0..3 (64 cols each)
    const int rb0  = wm * 4;                 // A 16-row block base
    const int mt   = blockIdx.y;
    const int blockM = mt * BM;
    const int blockN = blockIdx.x * BN;

    const int nv = g_cv;
    const __half* wsel = (blockM < nv) ? g_wv : g_wt;
    const char* gA  = (const char*)(g_x + (size_t)mt * NK * PANEL_H);
    const char* gB0 = (const char*)(wsel + (size_t)(2 * blockIdx.x)     * NK * PANEL_H);
    const char* gB1 = (const char*)(wsel + (size_t)(2 * blockIdx.x + 1) * NK * PANEL_H);

    const uint32_t sbase = smem_u32(dsmem);
    // b-frag addressing: global j-block jb = wn*8+j -> panel p = wn>>1,
    // within-panel block jbp = (wn&1)*8 + j
    const uint32_t bpan = (uint32_t)(APANEL_B + (wn >> 1) * BPANEL_B);
    const int jb_base = (wn & 1) * 8;

    float acc[4][8][4];
    #pragma unroll
    for (int i = 0; i < 4; i++)
        #pragma unroll
        for (int j = 0; j < 8; j++)
            #pragma unroll
            for (int c = 0; c < 4; c++) acc[i][j][c] = 0.f;

    auto BISSUE = [&](int kt) {
        const uint32_t sst = sbase + (kt & (BSTAGES - 1)) * STAGE_B;
        #pragma unroll
        for (int i = 0; i < 2; i++) {
            uint32_t off = (uint32_t)(i * 4096 + tid * 16);
            cp16(sst + off, gA + (size_t)kt * APANEL_B + off);
        }
        #pragma unroll
        for (int i = 0; i < 2; i++) {
            uint32_t off = (uint32_t)(i * 4096 + tid * 16);
            cp16(sst + APANEL_B + off, gB0 + (size_t)kt * BPANEL_B + off);
        }
        #pragma unroll
        for (int i = 0; i < 2; i++) {
            uint32_t off = (uint32_t)(i * 4096 + tid * 16);
            cp16(sst + APANEL_B + BPANEL_B + off, gB1 + (size_t)kt * BPANEL_B + off);
        }
        asm volatile("cp.async.commit_group;" ::: "memory");
    };

    // prologue
    BISSUE(0); BISSUE(1); BISSUE(2);

    for (int kt = 0; kt < NK; kt++) {
        if (kt < NK - 2)
            asm volatile("cp.async.wait_group 2;" ::: "memory");
        else if (kt == NK - 2)
            asm volatile("cp.async.wait_group 1;" ::: "memory");
        else
            asm volatile("cp.async.wait_group 0;" ::: "memory");
        __syncthreads();
        if (kt + 3 < NK) BISSUE(kt + 3);

        const char* stage = dsmem + (kt & (BSTAGES - 1)) * STAGE_B;

        #pragma unroll
        for (int ks = 0; ks < 2; ks++) {
            uint32_t a[4][4];
            #pragma unroll
            for (int i = 0; i < 4; i++) {
                uint4 v = *(const uint4*)(stage + ((rb0 + i) * 2 + ks) * 512
                                          + lane * 16);
                a[i][0] = v.x; a[i][1] = v.y; a[i][2] = v.z; a[i][3] = v.w;
            }
            uint32_t b[8][2];
            #pragma unroll
            for (int j = 0; j < 8; j++) {
                uint2 v = *(const uint2*)(stage + bpan
                                          + ((jb_base + j) * 2 + ks) * 256 + lane * 8);
                b[j][0] = v.x; b[j][1] = v.y;
            }
            #pragma unroll
            for (int i = 0; i < 4; i++)
                #pragma unroll
                for (int j = 0; j < 8; j++)
                    mma_f16(acc[i][j], a[i], b[j]);
        }
    }

    // epilogue: scatter live rows through perm
    #pragma unroll
    for (int i = 0; i < 4; i++) {
        int r = (rb0 + i) * 16 + grp;
        int s0 = blockM + r, s1 = blockM + r + 8;
        int d0 = ((s0 < nv) || (s0 >= nv + BM)) ? g_perm[s0] : -1;
        int d1 = ((s1 < nv) || (s1 >= nv + BM)) ? g_perm[s1] : -1;
        #pragma unroll
        for (int j = 0; j < 8; j++) {
            int col = blockN + wn * 64 + j * 8 + qid * 2;
            if (d0 >= 0)
                *(float2*)(out + (size_t)d0 * N_DIM + col) =
                    make_float2(acc[i][j][0], acc[i][j][1]);
            if (d1 >= 0)
                *(float2*)(out + (size_t)d1 * N_DIM + col) =
                    make_float2(acc[i][j][2], acc[i][j][3]);
        }
    }
}

// ------------------------------------------------------------- launch
extern "C" void kernel_launch(void* const* d_in, const int* in_sizes, int n_in,
                              void* d_out, int out_size)
{
    const float*         x    = (const float*)d_in[0];
    const unsigned char* mask = (const unsigned char*)d_in[1];
    const float*         Wv   = (const float*)d_in[2];
    const float*         Wt   = (const float*)d_in[3];
    float*               out  = (float*)d_out;

    static bool attr_set = false;
    if (!attr_set) {
        cudaFuncSetAttribute(gemm_kernel,
                             cudaFuncAttributeMaxDynamicSharedMemorySize, DYN_SMEM);
        attr_set = true;
    }

    k0_init<<<1, 1024>>>(mask);
    k12_assign<<<M_TOTAL / 256, 256>>>(mask);
    k3_xconv<<<dim3(NMT, NK), 256>>>(x);
    k4_wconv<<<dim3(N_DIM / 128, NK, 2), 256>>>(Wv, Wt);
    gemm_kernel<<<dim3(N_DIM / BN, NMT), THREADS, DYN_SMEM>>>(out);
}

// round 12
// speedup vs baseline: 1.1982x; 1.1982x over previous
#include <cuda_runtime.h>
#include <cuda_fp16.h>
#include <cstdint>

// y[m,n] = mask[m] ? x[m,:]·W_v[n,:] : x[m,:]·W_t[n,:]
// Mask-partitioned single GEMM, fp16 m16n8k16 mma.sync, fp32 accumulate.
// GEMM = proven R4 structure (128x128 CTA, 4 warps @64x64, frag-order smem,
// 4-stage cp.async) + tail-race fix. Prep = one-pass slot assign with
// 128-row dead gap (no count pass), MLP-batched x convert.

#define M_TOTAL 32768
#define K_DIM   1024
#define N_DIM   1024
#define BM 128
#define BN 128
#define BK 32
#define STAGES 4
#define NK (K_DIM / BK)              // 32 k-panels
#define THREADS 128
#define M_PAD 32896                  // 257 tiles * 128
#define NMT (M_PAD / BM)             // 257

#define PANEL_H  4096                // halves per 8KB panel
#define APANEL_B 8192
#define STAGE_B  16384               // A panel + B panel
#define DYN_SMEM (STAGES * STAGE_B)  // 64 KB

// ------------------------------------------------------------- device state
__device__ __half g_x[(size_t)M_PAD * K_DIM];    // [mtile][kpanel][frag order]
__device__ __half g_wv[(size_t)N_DIM * K_DIM];   // [ntile][kpanel][frag order]
__device__ __half g_wt[(size_t)N_DIM * K_DIM];
__device__ int   g_perm[M_PAD];                  // slot -> source row (live only)
__device__ int   g_cv, g_ct;
__device__ int   g_mask_is_u8;

// Slot map: visual -> [0, nv) ascending; dead gap [nv, nv+128);
// text -> [nv+128, M_PAD) descending. Tile t uses W_v iff 128*t < nv.

// ------------------------------------------------------------- helpers
__device__ __forceinline__ bool mask_at(const unsigned char* m, int i) {
    return g_mask_is_u8 ? (m[i] != 0) : (((const int*)m)[i] != 0);
}

__device__ __forceinline__ uint32_t smem_u32(const void* p) {
    uint32_t a;
    asm("{ .reg .u64 t; cvta.to.shared.u64 t, %1; cvt.u32.u64 %0, t; }"
        : "=r"(a) : "l"(p));
    return a;
}

__device__ __forceinline__ void cp16(uint32_t saddr, const void* g) {
    asm volatile("cp.async.cg.shared.global [%0], [%1], 16;"
                 :: "r"(saddr), "l"(g) : "memory");
}

__device__ __forceinline__ void mma_f16(float* d, const uint32_t* a, const uint32_t* b) {
    asm volatile(
        "mma.sync.aligned.m16n8k16.row.col.f32.f16.f16.f32 "
        "{%0,%1,%2,%3}, {%4,%5,%6,%7}, {%8,%9}, {%0,%1,%2,%3};"
        : "+f"(d[0]), "+f"(d[1]), "+f"(d[2]), "+f"(d[3])
        : "r"(a[0]), "r"(a[1]), "r"(a[2]), "r"(a[3]), "r"(b[0]), "r"(b[1]));
}

// ------------------------------------------------------------- prep kernels
__global__ void k0_init(const unsigned char* __restrict__ m) {
    __shared__ int found;
    int tid = threadIdx.x;
    if (tid == 0) { found = 0; g_cv = 0; g_ct = 0; }
    __syncthreads();
    int local = 0;
    for (int i = tid; i < 8192; i += 1024)
        if (m[4 * i + 1] | m[4 * i + 2] | m[4 * i + 3]) local = 1;
    if (local) atomicOr(&found, 1);
    __syncthreads();
    if (tid == 0) g_mask_is_u8 = found;
}

// K12: one-pass slot assignment (visual ascending, text descending).
__global__ void k12_assign(const unsigned char* __restrict__ m) {
    int tid = threadIdx.x;
    int row = blockIdx.x * 256 + tid;
    int lane = tid & 31;
    bool mv = mask_at(m, row);
    unsigned bal = __ballot_sync(0xffffffffu, mv);
    int cv = __popc(bal);
    int lpv = __popc(bal & ((1u << lane) - 1));
    int lpt = lane - lpv;
    int baseV = 0, baseT = 0;
    if (lane == 0) {
        baseV = atomicAdd(&g_cv, cv);
        baseT = atomicAdd(&g_ct, 32 - cv);
    }
    baseV = __shfl_sync(0xffffffffu, baseV, 0);
    baseT = __shfl_sync(0xffffffffu, baseT, 0);
    int slot = mv ? (baseV + lpv) : (M_PAD - 1 - (baseT + lpt));
    g_perm[slot] = row;
}

// K3: x gather + fp16 convert -> A panels in fragment order.
// MLP fix: batch all 4 gathered LDG.128s into regs before any STS.
__global__ void k3_xconv(const float* __restrict__ x) {
    __shared__ float sx[BM * BK];
    __shared__ int sperm[BM];
    const int mt = blockIdx.x, kp = blockIdx.y;
    const int tid = threadIdx.x;
    const int kbase = kp * BK;
    const int nv = g_cv;
    if (tid < BM) {
        int slot = mt * BM + tid;
        bool live = (slot < nv) || (slot >= nv + BM);
        sperm[tid] = live ? g_perm[slot] : -1;
    }
    __syncthreads();

    float4 v[4];
    #pragma unroll
    for (int i = 0; i < 4; i++) {
        int idx = i * 256 + tid;          // 0..1023
        int row = idx >> 3, q = idx & 7;
        int src = sperm[row];
        v[i] = (src >= 0)
            ? *(const float4*)(x + (size_t)src * K_DIM + kbase + q * 4)
            : make_float4(0.f, 0.f, 0.f, 0.f);
    }
    #pragma unroll
    for (int i = 0; i < 4; i++) {
        int idx = i * 256 + tid;
        int row = idx >> 3, q = idx & 7;
        *(float4*)(sx + row * BK + q * 4) = v[i];
    }
    __syncthreads();

    __half* dst = g_x + ((size_t)mt * NK + kp) * PANEL_H;
    #pragma unroll
    for (int i = 0; i < 2; i++) {
        int h0 = (i * 256 + tid) * 8;
        int b = h0 >> 8;
        int rb = b >> 1, ks = b & 1;
        int lane = (h0 >> 3) & 31;
        int grp = lane >> 2, qid = lane & 3;
        __half vals[8];
        #pragma unroll
        for (int reg = 0; reg < 4; reg++) {
            int row = rb * 16 + grp + 8 * (reg & 1);
            int k   = ks * 16 + 2 * qid + 8 * (reg >> 1);
            vals[reg * 2 + 0] = __float2half_rn(sx[row * BK + k]);
            vals[reg * 2 + 1] = __float2half_rn(sx[row * BK + k + 1]);
        }
        *(uint4*)(dst + h0) = *(const uint4*)vals;
    }
}

// K4: one weight matrix -> fp16 B panels in fragment order (launched twice).
__global__ void k4_wconv(const float* __restrict__ W, int which) {
    const int nt = blockIdx.x, kp = blockIdx.y;
    __half* dst = (which ? g_wt : g_wv) + ((size_t)nt * NK + kp) * PANEL_H;
    const int tid = threadIdx.x;
    const int kbase = kp * BK;
    #pragma unroll
    for (int q = 0; q < 2; q++) {
        int h0 = tid * 8 + q * 2048;
        __half vals[8];
        #pragma unroll
        for (int j = 0; j < 8; j++) {
            int h = h0 + j;
            int blk = h >> 7;
            int nb = blk >> 1, ks = blk & 1;
            int lane = (h >> 2) & 31;
            int v = h & 3;
            int grp = lane >> 2, qid = lane & 3;
            int n = nt * 128 + nb * 8 + grp;
            int k = kbase + ks * 16 + 2 * qid + 8 * (v >> 1) + (v & 1);
            vals[j] = __float2half_rn(W[(size_t)n * K_DIM + k]);
        }
        *(uint4*)(dst + h0) = *(const uint4*)vals;
    }
}

// ------------------------------------------------------------- GEMM (R4 core)
extern __shared__ __align__(128) char dsmem[];

__global__ __launch_bounds__(THREADS, 2)
void gemm_kernel(float* __restrict__ out)
{
    const int tid  = threadIdx.x;
    const int warp = tid >> 5;
    const int lane = tid & 31;
    const int grp  = lane >> 2;
    const int qid  = lane & 3;
    const int rb0  = (warp >> 1) * 4;        // A block base (64 rows)
    const int nb0  = (warp & 1) * 8;         // B block base (64 cols)
    const int blockN = blockIdx.x * BN;
    const int mt     = blockIdx.y;
    const int blockM = mt * BM;

    const int nv = g_cv;
    const char* gA = (const char*)(g_x + (size_t)mt * NK * PANEL_H);
    const char* gB = (const char*)(((blockM < nv) ? g_wv : g_wt)
                                   + (size_t)blockIdx.x * NK * PANEL_H);

    const uint32_t sbase = smem_u32(dsmem);

    float acc[4][8][4];
    #pragma unroll
    for (int i = 0; i < 4; i++)
        #pragma unroll
        for (int j = 0; j < 8; j++)
            #pragma unroll
            for (int c = 0; c < 4; c++) acc[i][j][c] = 0.f;

    auto ISSUE = [&](int kt) {
        const uint32_t sst = sbase + (kt & (STAGES - 1)) * STAGE_B;
        const char* srcA = gA + (size_t)kt * APANEL_B;
        const char* srcB = gB + (size_t)kt * APANEL_B;
        #pragma unroll
        for (int i = 0; i < 4; i++) {
            uint32_t off = (uint32_t)(i * 2048 + tid * 16);
            cp16(sst + off, srcA + off);
        }
        #pragma unroll
        for (int i = 0; i < 4; i++) {
            uint32_t off = (uint32_t)(i * 2048 + tid * 16);
            cp16(sst + APANEL_B + off, srcB + off);
        }
        asm volatile("cp.async.commit_group;" ::: "memory");
    };

    ISSUE(0); ISSUE(1); ISSUE(2);

    for (int kt = 0; kt < NK; kt++) {
        // Tail-correct wait: group kt must be complete past this point.
        if (kt < NK - 2)
            asm volatile("cp.async.wait_group 2;" ::: "memory");
        else if (kt == NK - 2)
            asm volatile("cp.async.wait_group 1;" ::: "memory");
        else
            asm volatile("cp.async.wait_group 0;" ::: "memory");
        __syncthreads();
        if (kt + STAGES - 1 < NK) ISSUE(kt + STAGES - 1);

        const char* stage = dsmem + (kt & (STAGES - 1)) * STAGE_B;
        const char* sB = stage + APANEL_B;

        #pragma unroll
        for (int ks = 0; ks < 2; ks++) {
            uint32_t a[4][4];
            #pragma unroll
            for (int i = 0; i < 4; i++) {
                uint4 v = *(const uint4*)(stage + ((rb0 + i) * 2 + ks) * 512
                                          + lane * 16);
                a[i][0] = v.x; a[i][1] = v.y; a[i][2] = v.z; a[i][3] = v.w;
            }
            uint32_t b[8][2];
            #pragma unroll
            for (int j = 0; j < 8; j++) {
                uint2 v = *(const uint2*)(sB + ((nb0 + j) * 2 + ks) * 256 + lane * 8);
                b[j][0] = v.x; b[j][1] = v.y;
            }
            #pragma unroll
            for (int i = 0; i < 4; i++)
                #pragma unroll
                for (int j = 0; j < 8; j++)
                    mma_f16(acc[i][j], a[i], b[j]);
        }
    }

    // epilogue: scatter live rows through perm
    #pragma unroll
    for (int i = 0; i < 4; i++) {
        int r = (rb0 + i) * 16 + grp;
        int s0 = blockM + r, s1 = blockM + r + 8;
        int d0 = ((s0 < nv) || (s0 >= nv + BM)) ? g_perm[s0] : -1;
        int d1 = ((s1 < nv) || (s1 >= nv + BM)) ? g_perm[s1] : -1;
        #pragma unroll
        for (int j = 0; j < 8; j++) {
            int col = blockN + (nb0 + j) * 8 + qid * 2;
            if (d0 >= 0)
                *(float2*)(out + (size_t)d0 * N_DIM + col) =
                    make_float2(acc[i][j][0], acc[i][j][1]);
            if (d1 >= 0)
                *(float2*)(out + (size_t)d1 * N_DIM + col) =
                    make_float2(acc[i][j][2], acc[i][j][3]);
        }
    }
}

// ------------------------------------------------------------- launch
extern "C" void kernel_launch(void* const* d_in, const int* in_sizes, int n_in,
                              void* d_out, int out_size)
{
    const float*         x    = (const float*)d_in[0];
    const unsigned char* mask = (const unsigned char*)d_in[1];
    const float*         Wv   = (const float*)d_in[2];
    const float*         Wt   = (const float*)d_in[3];
    float*               out  = (float*)d_out;

    static bool attr_set = false;
    if (!attr_set) {
        cudaFuncSetAttribute(gemm_kernel,
                             cudaFuncAttributeMaxDynamicSharedMemorySize, DYN_SMEM);
        attr_set = true;
    }

    // 6 launches, GEMM last -> ncu (-s 5 -c 1) lands on the GEMM
    k0_init<<<1, 1024>>>(mask);
    k12_assign<<<M_TOTAL / 256, 256>>>(mask);
    k3_xconv<<<dim3(NMT, NK), 256>>>(x);
    k4_wconv<<<dim3(N_DIM / 128, NK), 256>>>(Wv, 0);
    k4_wconv<<<dim3(N_DIM / 128, NK), 256>>>(Wt, 1);
    gemm_kernel<<<dim3(N_DIM / BN, NMT), THREADS, DYN_SMEM>>>(out);
}

// round 13
// speedup vs baseline: 1.2584x; 1.0502x over previous
#include <cuda_runtime.h>
#include <cuda_fp16.h>
#include <cstdint>

// y[m,n] = mask[m] ? x[m,:]·W_v[n,:] : x[m,:]·W_t[n,:]
// Mask-partitioned single GEMM, fp16 m16n8k16 mma.sync, fp32 accumulate.
// R13: R12 GEMM (proven R4 core + tail-correct waits) at 3 CTAs/SM
// (launch_bounds(128,3), 192KB smem/SM) for barrier/latency overlap.
// Prep: one-pass slot assign, MLP-batched x convert, merged W convert.

#define M_TOTAL 32768
#define K_DIM   1024
#define N_DIM   1024
#define BM 128
#define BN 128
#define BK 32
#define STAGES 4
#define NK (K_DIM / BK)              // 32 k-panels
#define THREADS 128
#define M_PAD 32896                  // 257 tiles * 128
#define NMT (M_PAD / BM)             // 257

#define PANEL_H  4096                // halves per 8KB panel
#define APANEL_B 8192
#define STAGE_B  16384               // A panel + B panel
#define DYN_SMEM (STAGES * STAGE_B)  // 64 KB

// ------------------------------------------------------------- device state
__device__ __half g_x[(size_t)M_PAD * K_DIM];    // [mtile][kpanel][frag order]
__device__ __half g_wv[(size_t)N_DIM * K_DIM];   // [ntile][kpanel][frag order]
__device__ __half g_wt[(size_t)N_DIM * K_DIM];
__device__ int   g_perm[M_PAD];                  // slot -> source row (live only)
__device__ int   g_cv, g_ct;
__device__ int   g_mask_is_u8;

// Slot map: visual -> [0, nv) ascending; dead gap [nv, nv+128);
// text -> [nv+128, M_PAD) descending. Tile t uses W_v iff 128*t < nv.

// ------------------------------------------------------------- helpers
__device__ __forceinline__ bool mask_at(const unsigned char* m, int i) {
    return g_mask_is_u8 ? (m[i] != 0) : (((const int*)m)[i] != 0);
}

__device__ __forceinline__ uint32_t smem_u32(const void* p) {
    uint32_t a;
    asm("{ .reg .u64 t; cvta.to.shared.u64 t, %1; cvt.u32.u64 %0, t; }"
        : "=r"(a) : "l"(p));
    return a;
}

__device__ __forceinline__ void cp16(uint32_t saddr, const void* g) {
    asm volatile("cp.async.cg.shared.global [%0], [%1], 16;"
                 :: "r"(saddr), "l"(g) : "memory");
}

__device__ __forceinline__ void mma_f16(float* d, const uint32_t* a, const uint32_t* b) {
    asm volatile(
        "mma.sync.aligned.m16n8k16.row.col.f32.f16.f16.f32 "
        "{%0,%1,%2,%3}, {%4,%5,%6,%7}, {%8,%9}, {%0,%1,%2,%3};"
        : "+f"(d[0]), "+f"(d[1]), "+f"(d[2]), "+f"(d[3])
        : "r"(a[0]), "r"(a[1]), "r"(a[2]), "r"(a[3]), "r"(b[0]), "r"(b[1]));
}

// ------------------------------------------------------------- prep kernels
__global__ void k0_init(const unsigned char* __restrict__ m) {
    __shared__ int found;
    int tid = threadIdx.x;
    if (tid == 0) { found = 0; g_cv = 0; g_ct = 0; }
    __syncthreads();
    int local = 0;
    for (int i = tid; i < 8192; i += 1024)
        if (m[4 * i + 1] | m[4 * i + 2] | m[4 * i + 3]) local = 1;
    if (local) atomicOr(&found, 1);
    __syncthreads();
    if (tid == 0) g_mask_is_u8 = found;
}

// K12: one-pass slot assignment (visual ascending, text descending).
__global__ void k12_assign(const unsigned char* __restrict__ m) {
    int tid = threadIdx.x;
    int row = blockIdx.x * 256 + tid;
    int lane = tid & 31;
    bool mv = mask_at(m, row);
    unsigned bal = __ballot_sync(0xffffffffu, mv);
    int cv = __popc(bal);
    int lpv = __popc(bal & ((1u << lane) - 1));
    int lpt = lane - lpv;
    int baseV = 0, baseT = 0;
    if (lane == 0) {
        baseV = atomicAdd(&g_cv, cv);
        baseT = atomicAdd(&g_ct, 32 - cv);
    }
    baseV = __shfl_sync(0xffffffffu, baseV, 0);
    baseT = __shfl_sync(0xffffffffu, baseT, 0);
    int slot = mv ? (baseV + lpv) : (M_PAD - 1 - (baseT + lpt));
    g_perm[slot] = row;
}

// K3: x gather + fp16 convert -> A panels in fragment order (MLP-batched).
__global__ void k3_xconv(const float* __restrict__ x) {
    __shared__ float sx[BM * BK];
    __shared__ int sperm[BM];
    const int mt = blockIdx.x, kp = blockIdx.y;
    const int tid = threadIdx.x;
    const int kbase = kp * BK;
    const int nv = g_cv;
    if (tid < BM) {
        int slot = mt * BM + tid;
        bool live = (slot < nv) || (slot >= nv + BM);
        sperm[tid] = live ? g_perm[slot] : -1;
    }
    __syncthreads();

    float4 v[4];
    #pragma unroll
    for (int i = 0; i < 4; i++) {
        int idx = i * 256 + tid;          // 0..1023
        int row = idx >> 3, q = idx & 7;
        int src = sperm[row];
        v[i] = (src >= 0)
            ? *(const float4*)(x + (size_t)src * K_DIM + kbase + q * 4)
            : make_float4(0.f, 0.f, 0.f, 0.f);
    }
    #pragma unroll
    for (int i = 0; i < 4; i++) {
        int idx = i * 256 + tid;
        int row = idx >> 3, q = idx & 7;
        *(float4*)(sx + row * BK + q * 4) = v[i];
    }
    __syncthreads();

    __half* dst = g_x + ((size_t)mt * NK + kp) * PANEL_H;
    #pragma unroll
    for (int i = 0; i < 2; i++) {
        int h0 = (i * 256 + tid) * 8;
        int b = h0 >> 8;
        int rb = b >> 1, ks = b & 1;
        int lane = (h0 >> 3) & 31;
        int grp = lane >> 2, qid = lane & 3;
        __half vals[8];
        #pragma unroll
        for (int reg = 0; reg < 4; reg++) {
            int row = rb * 16 + grp + 8 * (reg & 1);
            int k   = ks * 16 + 2 * qid + 8 * (reg >> 1);
            vals[reg * 2 + 0] = __float2half_rn(sx[row * BK + k]);
            vals[reg * 2 + 1] = __float2half_rn(sx[row * BK + k + 1]);
        }
        *(uint4*)(dst + h0) = *(const uint4*)vals;
    }
}

// K4: weights -> fp16 B panels in fragment order (z selects matrix).
__global__ void k4_wconv(const float* __restrict__ Wv, const float* __restrict__ Wt) {
    const int nt = blockIdx.x, kp = blockIdx.y;
    const float* W = blockIdx.z ? Wt : Wv;
    __half* dst = (blockIdx.z ? g_wt : g_wv) + ((size_t)nt * NK + kp) * PANEL_H;
    const int tid = threadIdx.x;
    const int kbase = kp * BK;
    #pragma unroll
    for (int q = 0; q < 2; q++) {
        int h0 = tid * 8 + q * 2048;
        __half vals[8];
        #pragma unroll
        for (int j = 0; j < 8; j++) {
            int h = h0 + j;
            int blk = h >> 7;
            int nb = blk >> 1, ks = blk & 1;
            int lane = (h >> 2) & 31;
            int v = h & 3;
            int grp = lane >> 2, qid = lane & 3;
            int n = nt * 128 + nb * 8 + grp;
            int k = kbase + ks * 16 + 2 * qid + 8 * (v >> 1) + (v & 1);
            vals[j] = __float2half_rn(W[(size_t)n * K_DIM + k]);
        }
        *(uint4*)(dst + h0) = *(const uint4*)vals;
    }
}

// ------------------------------------------------------------- GEMM (R4 core, 3 CTAs/SM)
extern __shared__ __align__(128) char dsmem[];

__global__ __launch_bounds__(THREADS, 3)
void gemm_kernel(float* __restrict__ out)
{
    const int tid  = threadIdx.x;
    const int warp = tid >> 5;
    const int lane = tid & 31;
    const int grp  = lane >> 2;
    const int qid  = lane & 3;
    const int rb0  = (warp >> 1) * 4;        // A block base (64 rows)
    const int nb0  = (warp & 1) * 8;         // B block base (64 cols)
    const int blockN = blockIdx.x * BN;
    const int mt     = blockIdx.y;
    const int blockM = mt * BM;

    const int nv = g_cv;
    const char* gA = (const char*)(g_x + (size_t)mt * NK * PANEL_H);
    const char* gB = (const char*)(((blockM < nv) ? g_wv : g_wt)
                                   + (size_t)blockIdx.x * NK * PANEL_H);

    const uint32_t sbase = smem_u32(dsmem);

    float acc[4][8][4];
    #pragma unroll
    for (int i = 0; i < 4; i++)
        #pragma unroll
        for (int j = 0; j < 8; j++)
            #pragma unroll
            for (int c = 0; c < 4; c++) acc[i][j][c] = 0.f;

    auto ISSUE = [&](int kt) {
        const uint32_t sst = sbase + (kt & (STAGES - 1)) * STAGE_B;
        const char* srcA = gA + (size_t)kt * APANEL_B;
        const char* srcB = gB + (size_t)kt * APANEL_B;
        #pragma unroll
        for (int i = 0; i < 4; i++) {
            uint32_t off = (uint32_t)(i * 2048 + tid * 16);
            cp16(sst + off, srcA + off);
        }
        #pragma unroll
        for (int i = 0; i < 4; i++) {
            uint32_t off = (uint32_t)(i * 2048 + tid * 16);
            cp16(sst + APANEL_B + off, srcB + off);
        }
        asm volatile("cp.async.commit_group;" ::: "memory");
    };

    ISSUE(0); ISSUE(1); ISSUE(2);

    for (int kt = 0; kt < NK; kt++) {
        // Tail-correct wait: group kt must be complete past this point.
        if (kt < NK - 2)
            asm volatile("cp.async.wait_group 2;" ::: "memory");
        else if (kt == NK - 2)
            asm volatile("cp.async.wait_group 1;" ::: "memory");
        else
            asm volatile("cp.async.wait_group 0;" ::: "memory");
        __syncthreads();
        if (kt + STAGES - 1 < NK) ISSUE(kt + STAGES - 1);

        const char* stage = dsmem + (kt & (STAGES - 1)) * STAGE_B;
        const char* sB = stage + APANEL_B;

        #pragma unroll
        for (int ks = 0; ks < 2; ks++) {
            uint32_t a[4][4];
            #pragma unroll
            for (int i = 0; i < 4; i++) {
                uint4 v = *(const uint4*)(stage + ((rb0 + i) * 2 + ks) * 512
                                          + lane * 16);
                a[i][0] = v.x; a[i][1] = v.y; a[i][2] = v.z; a[i][3] = v.w;
            }
            uint32_t b[8][2];
            #pragma unroll
            for (int j = 0; j < 8; j++) {
                uint2 v = *(const uint2*)(sB + ((nb0 + j) * 2 + ks) * 256 + lane * 8);
                b[j][0] = v.x; b[j][1] = v.y;
            }
            #pragma unroll
            for (int i = 0; i < 4; i++)
                #pragma unroll
                for (int j = 0; j < 8; j++)
                    mma_f16(acc[i][j], a[i], b[j]);
        }
    }

    // epilogue: scatter live rows through perm
    #pragma unroll
    for (int i = 0; i < 4; i++) {
        int r = (rb0 + i) * 16 + grp;
        int s0 = blockM + r, s1 = blockM + r + 8;
        int d0 = ((s0 < nv) || (s0 >= nv + BM)) ? g_perm[s0] : -1;
        int d1 = ((s1 < nv) || (s1 >= nv + BM)) ? g_perm[s1] : -1;
        #pragma unroll
        for (int j = 0; j < 8; j++) {
            int col = blockN + (nb0 + j) * 8 + qid * 2;
            if (d0 >= 0)
                *(float2*)(out + (size_t)d0 * N_DIM + col) =
                    make_float2(acc[i][j][0], acc[i][j][1]);
            if (d1 >= 0)
                *(float2*)(out + (size_t)d1 * N_DIM + col) =
                    make_float2(acc[i][j][2], acc[i][j][3]);
        }
    }
}

// ------------------------------------------------------------- launch
extern "C" void kernel_launch(void* const* d_in, const int* in_sizes, int n_in,
                              void* d_out, int out_size)
{
    const float*         x    = (const float*)d_in[0];
    const unsigned char* mask = (const unsigned char*)d_in[1];
    const float*         Wv   = (const float*)d_in[2];
    const float*         Wt   = (const float*)d_in[3];
    float*               out  = (float*)d_out;

    static bool attr_set = false;
    if (!attr_set) {
        cudaFuncSetAttribute(gemm_kernel,
                             cudaFuncAttributeMaxDynamicSharedMemorySize, DYN_SMEM);
        attr_set = true;
    }

    k0_init<<<1, 1024>>>(mask);
    k12_assign<<<M_TOTAL / 256, 256>>>(mask);
    k3_xconv<<<dim3(NMT, NK), 256>>>(x);
    k4_wconv<<<dim3(N_DIM / 128, NK, 2), 256>>>(Wv, Wt);
    gemm_kernel<<<dim3(N_DIM / BN, NMT), THREADS, DYN_SMEM>>>(out);
}